// round 10
// baseline (speedup 1.0000x reference)
#include <cuda_runtime.h>
#include <cstdint>

#define D_DIM 64
#define BT 64            // b per block
#define NT 64            // n per block
#define TPB 256
#define XSTRIDE 68       // x row stride (floats); 16B-aligned

// ---- packed f32x2 helpers (Blackwell FFMA2 path) ----
__device__ __forceinline__ uint64_t pk2(float lo, float hi) {
    uint64_t r; asm("mov.b64 %0, {%1, %2};" : "=l"(r) : "f"(lo), "f"(hi)); return r;
}
__device__ __forceinline__ void upk2(uint64_t v, float& lo, float& hi) {
    asm("mov.b64 {%0, %1}, %2;" : "=f"(lo), "=f"(hi) : "l"(v));
}
__device__ __forceinline__ uint64_t fma2(uint64_t a, uint64_t b, uint64_t c) {
    uint64_t d; asm("fma.rn.f32x2 %0, %1, %2, %3;" : "=l"(d) : "l"(a), "l"(b), "l"(c)); return d;
}
__device__ __forceinline__ uint64_t mul2(uint64_t a, uint64_t b) {
    uint64_t d; asm("mul.rn.f32x2 %0, %1, %2;" : "=l"(d) : "l"(a), "l"(b)); return d;
}
__device__ __forceinline__ uint64_t add2(uint64_t a, uint64_t b) {
    uint64_t d; asm("add.rn.f32x2 %0, %1, %2;" : "=l"(d) : "l"(a), "l"(b)); return d;
}

extern __shared__ float smem_dyn[];

// a/b layout: [n][d], row = 64 floats, 16B chunks XOR-swizzled by (n>>2)&7
// so the 16 rows (stride 4 in n) a warp touches per load spread across banks.
__device__ __forceinline__ int swz(int n, int d) {
    return (n << 6) | ((((d >> 2) ^ ((n >> 2) & 7)) << 2) | (d & 3));
}

__global__ __launch_bounds__(TPB, 2)
void wavelet_kernel(const float* __restrict__ x,
                    const float* __restrict__ centers,
                    const float* __restrict__ scales,
                    float* __restrict__ out, int N)
{
    float* sx = smem_dyn;                   // [BT][XSTRIDE]  b-major, d contiguous
    float* sa = sx + BT * XSTRIDE;          // [NT][64] swizzled: 1/s
    float* sb = sa + NT * 64;               // [NT][64] swizzled: -c/s

    const int tid = threadIdx.x;
    const int b0 = blockIdx.x * BT;
    const int n0 = blockIdx.y * NT;

    // x tile (coalesced)
    #pragma unroll 2
    for (int i = tid; i < BT * D_DIM; i += TPB) {
        int r = i >> 6, c = i & 63;
        sx[r * XSTRIDE + c] = x[(b0 + r) * D_DIM + c];
    }
    // a/b tiles in swizzled [n][d] layout
    #pragma unroll 4
    for (int i = tid; i < NT * D_DIM; i += TPB) {
        int n = i >> 6, d = i & 63;
        int g = (n0 + n) * D_DIM + d;
        float inv = 1.0f / scales[g];
        int sw = swz(n, d);
        sa[sw] = inv;
        sb[sw] = -centers[g] * inv;
    }
    __syncthreads();

    const int ng = tid & 15;   // n-group: 4 n's at ng*4
    const int bg = tid >> 4;   // b-group: 4 b's at bg*4
    const int swk = ng & 7;    // swizzle key for this thread's rows

    const float* xrow  = sx + (bg * 4) * XSTRIDE;
    const float* abase = sa + (ng * 4) * 64;
    const float* bbase = sb + (ng * 4) * 64;

    const uint64_t M1 = pk2(-1.0f, -1.0f);
    // accumulators packed over d-parity: p = prod(w), s = sum(w)
    uint64_t p[4][4], s[4][4];
    #pragma unroll
    for (int bi = 0; bi < 4; bi++)
        #pragma unroll
        for (int nj = 0; nj < 4; nj++) { p[bi][nj] = pk2(1.f, 1.f); s[bi][nj] = pk2(0.f, 0.f); }

    #pragma unroll
    for (int half = 0; half < 2; half++) {
        #pragma unroll 1
        for (int q = 0; q < 8; q++) {
            const int d0 = half * 32 + q * 4;
            const int co = (((d0 >> 2) ^ swk) << 2);

            ulonglong2 xv[4];
            #pragma unroll
            for (int bi = 0; bi < 4; bi++)
                xv[bi] = *reinterpret_cast<const ulonglong2*>(xrow + bi * XSTRIDE + d0);

            #pragma unroll
            for (int nj = 0; nj < 4; nj++) {
                const ulonglong2 av = *reinterpret_cast<const ulonglong2*>(abase + nj * 64 + co);
                const ulonglong2 bv = *reinterpret_cast<const ulonglong2*>(bbase + nj * 64 + co);
                #pragma unroll
                for (int bi = 0; bi < 4; bi++) {
                    uint64_t z0 = fma2(xv[bi].x, av.x, bv.x);   // (z_d, z_d+1)
                    uint64_t w0 = fma2(z0, z0, M1);             // z^2 - 1
                    p[bi][nj] = mul2(p[bi][nj], w0);
                    s[bi][nj] = add2(s[bi][nj], w0);
                    uint64_t z1 = fma2(xv[bi].y, av.y, bv.y);   // (z_d+2, z_d+3)
                    uint64_t w1 = fma2(z1, z1, M1);
                    p[bi][nj] = mul2(p[bi][nj], w1);
                    s[bi][nj] = add2(s[bi][nj], w1);
                }
            }
        }

        if (half == 0) {
            // range-control fold: apply Gaussian factor for first 32 dims
            #pragma unroll
            for (int bi = 0; bi < 4; bi++)
                #pragma unroll
                for (int nj = 0; nj < 4; nj++) {
                    float p0, p1, s0, s1;
                    upk2(p[bi][nj], p0, p1);
                    upk2(s[bi][nj], s0, s1);
                    float F = p0 * p1 * __expf(-0.5f * (s0 + s1 + 32.0f));
                    p[bi][nj] = pk2(F, 1.0f);
                    s[bi][nj] = pk2(0.f, 0.f);
                }
        }
    }

    // epilogue
    float* orow = out + (long)(b0 + bg * 4) * N + n0 + ng * 4;
    #pragma unroll
    for (int bi = 0; bi < 4; bi++) {
        float h[4];
        #pragma unroll
        for (int nj = 0; nj < 4; nj++) {
            float p0, p1, s0, s1;
            upk2(p[bi][nj], p0, p1);
            upk2(s[bi][nj], s0, s1);
            h[nj] = p0 * p1 * __expf(-0.5f * (s0 + s1 + 32.0f));
        }
        float4 v = {h[0], h[1], h[2], h[3]};
        *reinterpret_cast<float4*>(orow + (long)bi * N) = v;
    }
}

extern "C" void kernel_launch(void* const* d_in, const int* in_sizes, int n_in,
                              void* d_out, int out_size)
{
    const float* x       = (const float*)d_in[0];
    const float* centers = (const float*)d_in[1];
    const float* scales  = (const float*)d_in[2];
    float* out = (float*)d_out;

    const int B = in_sizes[0] / D_DIM;   // 8192
    const int N = in_sizes[1] / D_DIM;   // 512

    const int smem_bytes = (BT * XSTRIDE + 2 * NT * 64) * sizeof(float); // 50176
    static bool attr_set = false;
    if (!attr_set) {
        cudaFuncSetAttribute(wavelet_kernel,
                             cudaFuncAttributeMaxDynamicSharedMemorySize, smem_bytes);
        attr_set = true;
    }

    dim3 grid(B / BT, N / NT);           // (128, 8) = 1024 blocks
    wavelet_kernel<<<grid, TPB, smem_bytes>>>(x, centers, scales, out, N);
}

// round 11
// speedup vs baseline: 1.1524x; 1.1524x over previous
#include <cuda_runtime.h>
#include <cstdint>

#define D_DIM 64
#define BT 64            // b per block
#define NT 64            // n per block
#define TPB 256
#define XDSTRIDE 66      // x-dup row stride in u64 entries (528B: odd 16B count -> banks spread)
#define ASTRIDE 68       // a/b row stride (floats)

// ---- packed f32x2 helpers (Blackwell FFMA2 path) ----
__device__ __forceinline__ uint64_t pk2(float lo, float hi) {
    uint64_t r; asm("mov.b64 %0, {%1, %2};" : "=l"(r) : "f"(lo), "f"(hi)); return r;
}
__device__ __forceinline__ void upk2(uint64_t v, float& lo, float& hi) {
    asm("mov.b64 {%0, %1}, %2;" : "=f"(lo), "=f"(hi) : "l"(v));
}
__device__ __forceinline__ uint64_t fma2(uint64_t a, uint64_t b, uint64_t c) {
    uint64_t d; asm("fma.rn.f32x2 %0, %1, %2, %3;" : "=l"(d) : "l"(a), "l"(b), "l"(c)); return d;
}
__device__ __forceinline__ uint64_t mul2(uint64_t a, uint64_t b) {
    uint64_t d; asm("mul.rn.f32x2 %0, %1, %2;" : "=l"(d) : "l"(a), "l"(b)); return d;
}

extern __shared__ float smem_dyn[];

// One 4-dim block: 4 b x 4 n per thread (2 packed n-pairs).
// x comes from smem PRE-DUPLICATED as (x,x) u64 pairs: no pk2 MOVs in the loop.
__device__ __forceinline__ void do_dblk(const uint64_t* __restrict__ xdrow,
                                        const float* __restrict__ arow,
                                        const float* __restrict__ brow,
                                        int dblk, uint64_t M1,
                                        float (&s0)[4][2], float (&s1)[4][2],
                                        uint64_t (&pacc)[4][2])
{
    // stage x broadcast pairs: 2 LDS.128 per b-row
    uint64_t xp[4][4];
    #pragma unroll
    for (int bi = 0; bi < 4; bi++) {
        const ulonglong2 x01 = *reinterpret_cast<const ulonglong2*>(xdrow + bi * XDSTRIDE + dblk);
        const ulonglong2 x23 = *reinterpret_cast<const ulonglong2*>(xdrow + bi * XDSTRIDE + dblk + 2);
        xp[bi][0] = x01.x; xp[bi][1] = x01.y;
        xp[bi][2] = x23.x; xp[bi][3] = x23.y;
    }
    #pragma unroll
    for (int dd = 0; dd < 4; dd++) {
        const int off = (dblk + dd) * ASTRIDE;
        const ulonglong2 av = *reinterpret_cast<const ulonglong2*>(arow + off);
        const ulonglong2 bv = *reinterpret_cast<const ulonglong2*>(brow + off);
        const uint64_t A[2]  = {av.x, av.y};
        const uint64_t Bv[2] = {bv.x, bv.y};
        #pragma unroll
        for (int bi = 0; bi < 4; bi++) {
            #pragma unroll
            for (int k = 0; k < 2; k++) {
                uint64_t z = fma2(xp[bi][dd], A[k], Bv[k]);
                uint64_t w = fma2(z, z, M1);          // z^2 - 1
                float w0, w1;
                upk2(w, w0, w1);                      // pair-alias
                s0[bi][k] += w0;                      // scalar FADDs (R8 win)
                s1[bi][k] += w1;                      // sum z^2 = sum w + count
                pacc[bi][k] = mul2(pacc[bi][k], w);
            }
        }
    }
}

__global__ __launch_bounds__(TPB, 3)
void wavelet_kernel(const float* __restrict__ x,
                    const float* __restrict__ centers,
                    const float* __restrict__ scales,
                    float* __restrict__ out, int N)
{
    uint64_t* sxd = reinterpret_cast<uint64_t*>(smem_dyn);  // [BT][XDSTRIDE] dup pairs (x,x)
    float* sa = smem_dyn + BT * XDSTRIDE * 2;               // [D][ASTRIDE]  1/s (d-major)
    float* sb = sa + D_DIM * ASTRIDE;                       // [D][ASTRIDE]  -c/s

    const int tid = threadIdx.x;
    const int b0 = blockIdx.x * BT;
    const int n0 = blockIdx.y * NT;

    // x tile, duplicated into (x,x) u64 entries
    #pragma unroll 2
    for (int i = tid; i < BT * D_DIM; i += TPB) {
        int r = i >> 6, c = i & 63;
        float v = x[(b0 + r) * D_DIM + c];
        float2 f2 = make_float2(v, v);
        *reinterpret_cast<float2*>(&sxd[r * XDSTRIDE + c]) = f2;
    }
    // a/b tiles, transposed to [d][n]
    #pragma unroll 4
    for (int i = tid; i < NT * D_DIM; i += TPB) {
        int d = i & 63, n = i >> 6;
        int g = (n0 + n) * D_DIM + d;
        float inv = 1.0f / scales[g];
        sa[d * ASTRIDE + n] = inv;
        sb[d * ASTRIDE + n] = -centers[g] * inv;
    }
    __syncthreads();

    const int ng = tid & 15;   // 4 n's at ng*4
    const int bg = tid >> 4;   // 4 b's at bg*4

    const uint64_t* xdrow = sxd + (bg * 4) * XDSTRIDE;
    const float* arow = sa + ng * 4;
    const float* brow = sb + ng * 4;

    const uint64_t M1 = pk2(-1.0f, -1.0f);
    float s0[4][2], s1[4][2];
    uint64_t pacc[4][2];
    #pragma unroll
    for (int bi = 0; bi < 4; bi++)
        #pragma unroll
        for (int k = 0; k < 2; k++) {
            s0[bi][k] = 0.0f; s1[bi][k] = 0.0f;
            pacc[bi][k] = pk2(1.f, 1.f);
        }

    // first half: d = 0..31
    #pragma unroll 1
    for (int dblk = 0; dblk < 32; dblk += 4)
        do_dblk(xdrow, arow, brow, dblk, M1, s0, s1, pacc);

    // range-control fold: Gaussian factor for first 32 dims
    #pragma unroll
    for (int bi = 0; bi < 4; bi++)
        #pragma unroll
        for (int k = 0; k < 2; k++) {
            float p0, p1;
            upk2(pacc[bi][k], p0, p1);
            p0 *= __expf(-0.5f * (s0[bi][k] + 32.0f));
            p1 *= __expf(-0.5f * (s1[bi][k] + 32.0f));
            pacc[bi][k] = pk2(p0, p1);
            s0[bi][k] = 0.0f; s1[bi][k] = 0.0f;
        }

    // second half: d = 32..63
    #pragma unroll 1
    for (int dblk = 32; dblk < 64; dblk += 4)
        do_dblk(xdrow, arow, brow, dblk, M1, s0, s1, pacc);

    // epilogue
    float* orow = out + (long)(b0 + bg * 4) * N + n0 + ng * 4;
    #pragma unroll
    for (int bi = 0; bi < 4; bi++) {
        float h[4];
        #pragma unroll
        for (int k = 0; k < 2; k++) {
            float p0, p1;
            upk2(pacc[bi][k], p0, p1);
            h[2 * k]     = p0 * __expf(-0.5f * (s0[bi][k] + 32.0f));
            h[2 * k + 1] = p1 * __expf(-0.5f * (s1[bi][k] + 32.0f));
        }
        float4 v = {h[0], h[1], h[2], h[3]};
        *reinterpret_cast<float4*>(orow + (long)bi * N) = v;
    }
}

extern "C" void kernel_launch(void* const* d_in, const int* in_sizes, int n_in,
                              void* d_out, int out_size)
{
    const float* x       = (const float*)d_in[0];
    const float* centers = (const float*)d_in[1];
    const float* scales  = (const float*)d_in[2];
    float* out = (float*)d_out;

    const int B = in_sizes[0] / D_DIM;   // 8192
    const int N = in_sizes[1] / D_DIM;   // 512

    // x-dup 64*66*8 = 33792 B, a/b 2*64*68*4 = 34816 B -> 68608 B
    const int smem_bytes = BT * XDSTRIDE * 8 + 2 * D_DIM * ASTRIDE * 4;
    static bool attr_set = false;
    if (!attr_set) {
        cudaFuncSetAttribute(wavelet_kernel,
                             cudaFuncAttributeMaxDynamicSharedMemorySize, smem_bytes);
        attr_set = true;
    }

    dim3 grid(B / BT, N / NT);           // (128, 8) = 1024 blocks
    wavelet_kernel<<<grid, TPB, smem_bytes>>>(x, centers, scales, out, N);
}